// round 1
// baseline (speedup 1.0000x reference)
#include <cuda_runtime.h>
#include <cstdint>

#define N_NODES 50000
#define E_EDGES 800000
#define IN_F    128
#define HID_F   256
#define OUT_F   128

// ---------------- device scratch (no cudaMalloc allowed) ----------------
__device__ int   g_deg_out[N_NODES];
__device__ int   g_deg_in[N_NODES];
__device__ float g_out_isqrt[N_NODES];
__device__ float g_in_isqrt[N_NODES];
__device__ float g_m1[(size_t)N_NODES * IN_F];    // layer1 aggregated input
__device__ float g_t1[(size_t)N_NODES * HID_F];   // relu(m1*in_isqrt @ W1 + b1)
__device__ float g_g [(size_t)N_NODES * OUT_F];   // (t1*out_isqrt) @ W2

// ---------------- degree kernels ----------------
__global__ void k_deg_init() {
    int i = blockIdx.x * blockDim.x + threadIdx.x;
    if (i < N_NODES) { g_deg_out[i] = 1; g_deg_in[i] = 1; }  // self-loops
}

__global__ void k_deg_count(const int* __restrict__ ei) {
    int e = blockIdx.x * blockDim.x + threadIdx.x;
    if (e < E_EDGES) {
        atomicAdd(&g_deg_out[ei[e]], 1);
        atomicAdd(&g_deg_in[ei[E_EDGES + e]], 1);
    }
}

__global__ void k_isqrt() {
    int i = blockIdx.x * blockDim.x + threadIdx.x;
    if (i < N_NODES) {
        g_out_isqrt[i] = rsqrtf((float)g_deg_out[i]);
        g_in_isqrt[i]  = rsqrtf((float)g_deg_in[i]);
    }
}

// ---------------- init m1 with self-loop contribution: m1[v] = x[v]*out_isqrt[v] ----------------
__global__ void k_init_m1(const float* __restrict__ x) {
    int idx = blockIdx.x * blockDim.x + threadIdx.x;   // over N*32 float4s
    if (idx < N_NODES * (IN_F / 4)) {
        int v = idx >> 5;
        float s = g_out_isqrt[v];
        float4 a = reinterpret_cast<const float4*>(x)[idx];
        a.x *= s; a.y *= s; a.z *= s; a.w *= s;
        reinterpret_cast<float4*>(g_m1)[idx] = a;
    }
}

// ---------------- 128-wide edge aggregation: one warp per edge, red.v4 ----------------
template <bool SCALE_SRC>
__global__ void k_agg128(const int* __restrict__ src, const int* __restrict__ dst,
                         const float* __restrict__ feat, float* __restrict__ out) {
    int gt = blockIdx.x * blockDim.x + threadIdx.x;
    int e = gt >> 5;
    int lane = threadIdx.x & 31;
    if (e >= E_EDGES) return;
    int s = src[e];
    int d = dst[e];
    float4 a = reinterpret_cast<const float4*>(feat + (size_t)s * 128)[lane];
    if (SCALE_SRC) {
        float sc = g_out_isqrt[s];
        a.x *= sc; a.y *= sc; a.z *= sc; a.w *= sc;
    }
    float* o = out + (size_t)d * 128 + lane * 4;
    asm volatile("red.global.add.v4.f32 [%0], {%1, %2, %3, %4};"
                 :: "l"(o), "f"(a.x), "f"(a.y), "f"(a.z), "f"(a.w) : "memory");
}

// ---------------- tiled SGEMM with per-row pre-scale, optional bias/relu/dup-store ----------------
// C[M,Nc] = (rowscale[m] * A[m,:]) @ W[K,Nc]  (+bias) (relu)
template <bool RELU, bool BIAS, bool DUP>
__global__ __launch_bounds__(256)
void k_gemm_rowscale(const float* __restrict__ A, const float* __restrict__ W,
                     const float* __restrict__ rowscale, const float* __restrict__ bias,
                     float* __restrict__ C, float* __restrict__ C2,
                     int M, int K, int Nc) {
    constexpr int BM = 64, BN = 64, BK = 16;
    __shared__ float As[BK][BM];      // transposed A tile
    __shared__ float Ws[BK][BN];

    const int tid = threadIdx.x;
    const int tx = tid & 15;          // 0..15 -> N direction (x4)
    const int ty = tid >> 4;          // 0..15 -> M direction (x4)
    const int m0 = blockIdx.y * BM;
    const int n0 = blockIdx.x * BN;

    // A-load mapping: one float4 per thread
    const int ar = tid >> 2;             // 0..63 row within tile
    const int akc = (tid & 3) << 2;      // 0,4,8,12 k within tile
    // W-load mapping
    const int wkr = tid >> 4;            // 0..15
    const int wnc = (tid & 15) << 2;     // 0..60

    float acc[4][4] = {};

    for (int k0 = 0; k0 < K; k0 += BK) {
        // load A tile (scaled), transposed into As[k][m]
        {
            int arow = m0 + ar;
            float4 av = make_float4(0.f, 0.f, 0.f, 0.f);
            if (arow < M) {
                av = *reinterpret_cast<const float4*>(&A[(size_t)arow * K + k0 + akc]);
                float s = rowscale[arow];
                av.x *= s; av.y *= s; av.z *= s; av.w *= s;
            }
            As[akc + 0][ar] = av.x;
            As[akc + 1][ar] = av.y;
            As[akc + 2][ar] = av.z;
            As[akc + 3][ar] = av.w;
        }
        // load W tile
        *reinterpret_cast<float4*>(&Ws[wkr][wnc]) =
            *reinterpret_cast<const float4*>(&W[(size_t)(k0 + wkr) * Nc + n0 + wnc]);
        __syncthreads();

        #pragma unroll
        for (int k = 0; k < BK; k++) {
            float4 a4 = *reinterpret_cast<const float4*>(&As[k][ty << 2]);
            float4 b4 = *reinterpret_cast<const float4*>(&Ws[k][tx << 2]);
            float a[4] = {a4.x, a4.y, a4.z, a4.w};
            float b[4] = {b4.x, b4.y, b4.z, b4.w};
            #pragma unroll
            for (int i = 0; i < 4; i++)
                #pragma unroll
                for (int j = 0; j < 4; j++)
                    acc[i][j] = fmaf(a[i], b[j], acc[i][j]);
        }
        __syncthreads();
    }

    // epilogue
    const int row0 = m0 + (ty << 2);
    const int col = n0 + (tx << 2);
    float4 bv = make_float4(0.f, 0.f, 0.f, 0.f);
    if (BIAS) bv = *reinterpret_cast<const float4*>(&bias[col]);
    #pragma unroll
    for (int i = 0; i < 4; i++) {
        int row = row0 + i;
        if (row < M) {
            float4 c = make_float4(acc[i][0], acc[i][1], acc[i][2], acc[i][3]);
            if (BIAS) { c.x += bv.x; c.y += bv.y; c.z += bv.z; c.w += bv.w; }
            if (RELU) {
                c.x = fmaxf(c.x, 0.f); c.y = fmaxf(c.y, 0.f);
                c.z = fmaxf(c.z, 0.f); c.w = fmaxf(c.w, 0.f);
            }
            *reinterpret_cast<float4*>(&C[(size_t)row * Nc + col]) = c;
            if (DUP)
                *reinterpret_cast<float4*>(&C2[(size_t)row * Nc + col]) = c;
        }
    }
}

// ---------------- finalize: out = out * in_isqrt[row] + b2 ----------------
__global__ void k_finalize(float* __restrict__ out, const float* __restrict__ b2) {
    int idx = blockIdx.x * blockDim.x + threadIdx.x;   // over N*32 float4s
    if (idx < N_NODES * (OUT_F / 4)) {
        int v = idx >> 5;
        int f4 = idx & 31;
        float s = g_in_isqrt[v];
        float4 c = reinterpret_cast<float4*>(out)[idx];
        float4 b = reinterpret_cast<const float4*>(b2)[f4];
        c.x = fmaf(c.x, s, b.x);
        c.y = fmaf(c.y, s, b.y);
        c.z = fmaf(c.z, s, b.z);
        c.w = fmaf(c.w, s, b.w);
        reinterpret_cast<float4*>(out)[idx] = c;
    }
}

// ---------------- launch ----------------
extern "C" void kernel_launch(void* const* d_in, const int* in_sizes, int n_in,
                              void* d_out, int out_size) {
    const float* x  = (const float*)d_in[0];
    const int*   ei = (const int*)d_in[1];        // [2, E]: row0 = src, row1 = dst
    const float* W1 = (const float*)d_in[2];
    const float* b1 = (const float*)d_in[3];
    const float* W2 = (const float*)d_in[4];
    const float* b2 = (const float*)d_in[5];
    float* out = (float*)d_out;

    const int* src = ei;
    const int* dst = ei + E_EDGES;

    float* m1; cudaGetSymbolAddress((void**)&m1, g_m1);
    float* t1; cudaGetSymbolAddress((void**)&t1, g_t1);
    float* gg; cudaGetSymbolAddress((void**)&gg, g_g);
    float* in_isqrt;  cudaGetSymbolAddress((void**)&in_isqrt,  g_in_isqrt);
    float* out_isqrt; cudaGetSymbolAddress((void**)&out_isqrt, g_out_isqrt);

    // degrees
    k_deg_init<<<(N_NODES + 255) / 256, 256>>>();
    k_deg_count<<<(E_EDGES + 255) / 256, 256>>>(ei);
    k_isqrt<<<(N_NODES + 255) / 256, 256>>>();

    // layer 1: aggregate 128-dim scaled x
    k_init_m1<<<(N_NODES * 32 + 255) / 256, 256>>>(x);
    k_agg128<true><<<(E_EDGES * 32 + 255) / 256, 256>>>(src, dst, x, m1);

    // t1 = relu((m1 * in_isqrt) @ W1 + b1)   [N, 256]
    {
        dim3 grid(HID_F / 64, (N_NODES + 63) / 64);
        k_gemm_rowscale<true, true, false><<<grid, 256>>>(
            m1, W1, in_isqrt, b1, t1, nullptr, N_NODES, IN_F, HID_F);
    }

    // g = (t1 * out_isqrt) @ W2   [N, 128]; also self-loop-init d_out = g
    {
        dim3 grid(OUT_F / 64, (N_NODES + 63) / 64);
        k_gemm_rowscale<false, false, true><<<grid, 256>>>(
            t1, W2, out_isqrt, nullptr, gg, out, N_NODES, HID_F, OUT_F);
    }

    // layer 2 aggregate 128-dim g into d_out
    k_agg128<false><<<(E_EDGES * 32 + 255) / 256, 256>>>(src, dst, gg, out);

    // out = out * in_isqrt + b2
    k_finalize<<<(N_NODES * 32 + 255) / 256, 256>>>(out, b2);
}